// round 1
// baseline (speedup 1.0000x reference)
#include <cuda_runtime.h>
#include <stdint.h>
#include <math.h>

#define B_  2
#define S_  2048
#define D_  1024
#define H_  16
#define HD_ 64

// Scratch (allocation-free rule: __device__ globals)
__device__ float g_q[(size_t)B_ * H_ * S_ * HD_];
__device__ float g_k[(size_t)B_ * H_ * S_ * HD_];
__device__ float g_v[(size_t)B_ * H_ * S_ * HD_];
__device__ float g_att[(size_t)B_ * S_ * D_];

__device__ __forceinline__ uint32_t f2tf(float x) {
    uint32_t u;
    asm("cvt.rna.tf32.f32 %0, %1;" : "=r"(u) : "f"(x));
    return u;
}

__device__ __forceinline__ void mma_tf32(float* c, const uint32_t* a, uint32_t b0, uint32_t b1) {
    asm volatile(
        "mma.sync.aligned.m16n8k8.row.col.f32.tf32.tf32.f32 "
        "{%0,%1,%2,%3}, {%4,%5,%6,%7}, {%8,%9}, {%0,%1,%2,%3};"
        : "+f"(c[0]), "+f"(c[1]), "+f"(c[2]), "+f"(c[3])
        : "r"(a[0]), "r"(a[1]), "r"(a[2]), "r"(a[3]), "r"(b0), "r"(b1));
}

// ============================================================================
// Projection: out[b,h,s,:] = X[b,s,:] @ W[h] + bias[h]
// Block tile: M=128 (seq rows) x N=64 (one head's full output). 256 threads.
// Warp layout 4(M) x 2(N): warp tile 32x32 -> 2x4 m16n8 frags.
// ============================================================================
__global__ __launch_bounds__(256) void proj_kernel(const float* __restrict__ X,
                                                   const float* __restrict__ W,
                                                   const float* __restrict__ bias,
                                                   int which)
{
    float* out = (which == 0) ? g_q : ((which == 1) ? g_k : g_v);

    const int mt = blockIdx.x;           // 0..15  (S/128)
    const int bh = blockIdx.y;           // 0..31  (B*H)
    const int b  = bh / H_;
    const int h  = bh % H_;

    const float* Xb = X    + (size_t)b * S_ * D_;
    const float* Wh = W    + (size_t)h * D_ * HD_;
    const float* bi = bias + (size_t)h * HD_;
    float*       Ob = out  + (size_t)bh * S_ * HD_;

    __shared__ float As[128][36];   // [m][k], pad 36 (mult of 4 for float4)
    __shared__ float Bs[32][68];    // [k][n], pad 68

    const int tid  = threadIdx.x;
    const int warp = tid >> 5;
    const int lane = tid & 31;
    const int g    = lane >> 2;     // groupID 0..7
    const int t    = lane & 3;      // threadID-in-group 0..3
    const int wm   = warp >> 1;     // 0..3
    const int wn   = warp & 1;      // 0..1

    float acc[2][4][4];
    #pragma unroll
    for (int i = 0; i < 2; i++)
        #pragma unroll
        for (int j = 0; j < 4; j++)
            #pragma unroll
            for (int r = 0; r < 4; r++)
                acc[i][j][r] = 0.0f;

    for (int k0 = 0; k0 < D_; k0 += 32) {
        // Load A tile: 128 rows x 32 cols
        {
            int r  = tid >> 3;            // 0..31
            int c4 = (tid & 7) * 4;       // 0..28
            #pragma unroll
            for (int i = 0; i < 4; i++) {
                float4 v = *(const float4*)&Xb[(size_t)(mt * 128 + r + i * 32) * D_ + k0 + c4];
                *(float4*)&As[r + i * 32][c4] = v;
            }
        }
        // Load B tile: 32 rows x 64 cols
        {
            int r  = tid >> 4;            // 0..15
            int c4 = (tid & 15) * 4;      // 0..60
            #pragma unroll
            for (int i = 0; i < 2; i++) {
                float4 v = *(const float4*)&Wh[(size_t)(k0 + r + i * 16) * HD_ + c4];
                *(float4*)&Bs[r + i * 16][c4] = v;
            }
        }
        __syncthreads();

        #pragma unroll
        for (int kk = 0; kk < 32; kk += 8) {
            uint32_t a[2][4];
            #pragma unroll
            for (int i = 0; i < 2; i++) {
                int m = wm * 32 + i * 16;
                a[i][0] = f2tf(As[m + g    ][kk + t    ]);
                a[i][1] = f2tf(As[m + g + 8][kk + t    ]);
                a[i][2] = f2tf(As[m + g    ][kk + t + 4]);
                a[i][3] = f2tf(As[m + g + 8][kk + t + 4]);
            }
            uint32_t bf[4][2];
            #pragma unroll
            for (int j = 0; j < 4; j++) {
                int n = wn * 32 + j * 8;
                bf[j][0] = f2tf(Bs[kk + t    ][n + g]);
                bf[j][1] = f2tf(Bs[kk + t + 4][n + g]);
            }
            #pragma unroll
            for (int i = 0; i < 2; i++)
                #pragma unroll
                for (int j = 0; j < 4; j++)
                    mma_tf32(acc[i][j], a[i], bf[j][0], bf[j][1]);
        }
        __syncthreads();
    }

    // Epilogue: add bias, store float2
    #pragma unroll
    for (int i = 0; i < 2; i++) {
        int row = mt * 128 + wm * 32 + i * 16 + g;
        #pragma unroll
        for (int j = 0; j < 4; j++) {
            int col = wn * 32 + j * 8 + 2 * t;
            float b0 = bi[col], b1 = bi[col + 1];
            float2 v0 = make_float2(acc[i][j][0] + b0, acc[i][j][1] + b1);
            float2 v1 = make_float2(acc[i][j][2] + b0, acc[i][j][3] + b1);
            *(float2*)&Ob[(size_t)row * HD_ + col]       = v0;
            *(float2*)&Ob[(size_t)(row + 8) * HD_ + col] = v1;
        }
    }
}

// ============================================================================
// Flash attention: one block = (b,h, 64-row Q tile). 128 threads (4 warps).
// Each warp owns 16 complete q-rows -> softmax stats warp-local.
// K/V processed in 32-key tiles. P relayout via shared (C-frag -> A-frag).
// ============================================================================
__global__ __launch_bounds__(128) void attn_kernel()
{
    const int qt = blockIdx.x;          // 0..31 (S/64)
    const int bh = blockIdx.y;          // 0..31
    const int b  = bh / H_;
    const int h  = bh % H_;
    const int q0 = qt * 64;

    const float* Qg = g_q + (size_t)bh * S_ * HD_;
    const float* Kg = g_k + (size_t)bh * S_ * HD_;
    const float* Vg = g_v + (size_t)bh * S_ * HD_;

    __shared__ float Qs[64][68];
    __shared__ float Ks[32][68];
    __shared__ float Vs[32][68];
    __shared__ float Ps[64][36];

    const int tid  = threadIdx.x;
    const int warp = tid >> 5;          // 0..3
    const int lane = tid & 31;
    const int g    = lane >> 2;
    const int t    = lane & 3;
    const int wrow = warp * 16;

    // Load Q tile (64 x 64)
    {
        int r  = tid >> 4;              // 0..7
        int c4 = (tid & 15) * 4;
        #pragma unroll
        for (int i = 0; i < 8; i++) {
            int rr = r + i * 8;
            *(float4*)&Qs[rr][c4] = *(const float4*)&Qg[(size_t)(q0 + rr) * HD_ + c4];
        }
    }

    float o[8][4];
    #pragma unroll
    for (int j = 0; j < 8; j++)
        #pragma unroll
        for (int r = 0; r < 4; r++) o[j][r] = 0.0f;
    float m0 = -INFINITY, m1 = -INFINITY;
    float l0 = 0.0f, l1 = 0.0f;

    for (int kt = 0; kt < S_ / 32; kt++) {
        __syncthreads();   // prev iter done reading Ks/Vs (iter0: Qs ready)
        // Load K/V tiles (32 x 64 each)
        {
            int r  = tid >> 4;
            int c4 = (tid & 15) * 4;
            #pragma unroll
            for (int i = 0; i < 4; i++) {
                int rr = r + i * 8;
                size_t go = (size_t)(kt * 32 + rr) * HD_ + c4;
                *(float4*)&Ks[rr][c4] = *(const float4*)&Kg[go];
                *(float4*)&Vs[rr][c4] = *(const float4*)&Vg[go];
            }
        }
        __syncthreads();

        // S = Q K^T (16 q-rows x 32 keys per warp)
        float s[4][4];
        #pragma unroll
        for (int j = 0; j < 4; j++)
            #pragma unroll
            for (int r = 0; r < 4; r++) s[j][r] = 0.0f;

        #pragma unroll
        for (int kk = 0; kk < 64; kk += 8) {
            uint32_t a[4];
            a[0] = f2tf(Qs[wrow + g    ][kk + t    ]);
            a[1] = f2tf(Qs[wrow + g + 8][kk + t    ]);
            a[2] = f2tf(Qs[wrow + g    ][kk + t + 4]);
            a[3] = f2tf(Qs[wrow + g + 8][kk + t + 4]);
            #pragma unroll
            for (int j = 0; j < 4; j++) {
                uint32_t b0 = f2tf(Ks[j * 8 + g][kk + t    ]);
                uint32_t b1 = f2tf(Ks[j * 8 + g][kk + t + 4]);
                mma_tf32(s[j], a, b0, b1);
            }
        }

        // Online softmax (rows g and g+8, warp-local via tig shuffles)
        const float sc = 0.125f;  // 1/sqrt(64)
        float mx0 = -INFINITY, mx1 = -INFINITY;
        #pragma unroll
        for (int j = 0; j < 4; j++) {
            s[j][0] *= sc; s[j][1] *= sc; s[j][2] *= sc; s[j][3] *= sc;
            mx0 = fmaxf(mx0, fmaxf(s[j][0], s[j][1]));
            mx1 = fmaxf(mx1, fmaxf(s[j][2], s[j][3]));
        }
        mx0 = fmaxf(mx0, __shfl_xor_sync(0xffffffff, mx0, 1));
        mx0 = fmaxf(mx0, __shfl_xor_sync(0xffffffff, mx0, 2));
        mx1 = fmaxf(mx1, __shfl_xor_sync(0xffffffff, mx1, 1));
        mx1 = fmaxf(mx1, __shfl_xor_sync(0xffffffff, mx1, 2));

        float mn0 = fmaxf(m0, mx0), mn1 = fmaxf(m1, mx1);
        float al0 = __expf(m0 - mn0), al1 = __expf(m1 - mn1);
        m0 = mn0; m1 = mn1;

        float sum0 = 0.0f, sum1 = 0.0f;
        #pragma unroll
        for (int j = 0; j < 4; j++) {
            float p00 = __expf(s[j][0] - mn0);
            float p01 = __expf(s[j][1] - mn0);
            float p10 = __expf(s[j][2] - mn1);
            float p11 = __expf(s[j][3] - mn1);
            sum0 += p00 + p01;
            sum1 += p10 + p11;
            *(float2*)&Ps[wrow + g    ][j * 8 + 2 * t] = make_float2(p00, p01);
            *(float2*)&Ps[wrow + g + 8][j * 8 + 2 * t] = make_float2(p10, p11);
        }
        sum0 += __shfl_xor_sync(0xffffffff, sum0, 1);
        sum0 += __shfl_xor_sync(0xffffffff, sum0, 2);
        sum1 += __shfl_xor_sync(0xffffffff, sum1, 1);
        sum1 += __shfl_xor_sync(0xffffffff, sum1, 2);
        l0 = l0 * al0 + sum0;
        l1 = l1 * al1 + sum1;

        #pragma unroll
        for (int j = 0; j < 8; j++) {
            o[j][0] *= al0; o[j][1] *= al0;
            o[j][2] *= al1; o[j][3] *= al1;
        }
        __syncwarp();   // Ps rows are warp-private; order writes before reads

        // O += P V  (K-dim = 32 keys, N = 64 head dims)
        #pragma unroll
        for (int kk = 0; kk < 32; kk += 8) {
            uint32_t a[4];
            a[0] = f2tf(Ps[wrow + g    ][kk + t    ]);
            a[1] = f2tf(Ps[wrow + g + 8][kk + t    ]);
            a[2] = f2tf(Ps[wrow + g    ][kk + t + 4]);
            a[3] = f2tf(Ps[wrow + g + 8][kk + t + 4]);
            #pragma unroll
            for (int j = 0; j < 8; j++) {
                uint32_t b0 = f2tf(Vs[kk + t    ][j * 8 + g]);
                uint32_t b1 = f2tf(Vs[kk + t + 4][j * 8 + g]);
                mma_tf32(o[j], a, b0, b1);
            }
        }
    }

    // Epilogue: normalize, scatter into [B,S,D] (concat heads)
    float inv0 = 1.0f / l0, inv1 = 1.0f / l1;
    #pragma unroll
    for (int j = 0; j < 8; j++) {
        int srow = q0 + wrow + g;
        int col  = h * HD_ + j * 8 + 2 * t;
        *(float2*)&g_att[((size_t)b * S_ + srow) * D_ + col] =
            make_float2(o[j][0] * inv0, o[j][1] * inv0);
        *(float2*)&g_att[((size_t)b * S_ + srow + 8) * D_ + col] =
            make_float2(o[j][2] * inv1, o[j][3] * inv1);
    }
}

// ============================================================================
// LayerNorm over last dim (1024). One block (256 thr) per row; float4 I/O.
// ============================================================================
__global__ __launch_bounds__(256) void ln_kernel(const float* __restrict__ gamma,
                                                 const float* __restrict__ beta,
                                                 float* __restrict__ out)
{
    const int row = blockIdx.x;
    const float* x = g_att + (size_t)row * D_;
    float*       y = out   + (size_t)row * D_;

    const int tid = threadIdx.x;
    float4 v = *(const float4*)&x[tid * 4];
    float sum = v.x + v.y + v.z + v.w;
    float sq  = v.x * v.x + v.y * v.y + v.z * v.z + v.w * v.w;

    #pragma unroll
    for (int off = 16; off > 0; off >>= 1) {
        sum += __shfl_down_sync(0xffffffff, sum, off);
        sq  += __shfl_down_sync(0xffffffff, sq,  off);
    }
    __shared__ float rs[8], rq[8], stats[2];
    int warp = tid >> 5, lane = tid & 31;
    if (lane == 0) { rs[warp] = sum; rq[warp] = sq; }
    __syncthreads();
    if (tid == 0) {
        float ts = 0.0f, tq = 0.0f;
        #pragma unroll
        for (int i = 0; i < 8; i++) { ts += rs[i]; tq += rq[i]; }
        float mean = ts * (1.0f / D_);
        float var  = tq * (1.0f / D_) - mean * mean;
        stats[0] = mean;
        stats[1] = rsqrtf(var + 1e-5f);
    }
    __syncthreads();
    float mean = stats[0], rstd = stats[1];

    float4 gm = *(const float4*)&gamma[tid * 4];
    float4 bt = *(const float4*)&beta[tid * 4];
    float4 r;
    r.x = (v.x - mean) * rstd * gm.x + bt.x;
    r.y = (v.y - mean) * rstd * gm.y + bt.y;
    r.z = (v.z - mean) * rstd * gm.z + bt.z;
    r.w = (v.w - mean) * rstd * gm.w + bt.w;
    *(float4*)&y[tid * 4] = r;
}

extern "C" void kernel_launch(void* const* d_in, const int* in_sizes, int n_in,
                              void* d_out, int out_size)
{
    (void)in_sizes; (void)n_in; (void)out_size;
    const float* queries = (const float*)d_in[0];
    const float* keys    = (const float*)d_in[1];
    const float* values  = (const float*)d_in[2];
    const float* Wq      = (const float*)d_in[3];
    const float* bq      = (const float*)d_in[4];
    const float* Wk      = (const float*)d_in[5];
    const float* bk      = (const float*)d_in[6];
    const float* Wv      = (const float*)d_in[7];
    const float* bv      = (const float*)d_in[8];
    const float* gamma   = (const float*)d_in[9];
    const float* beta    = (const float*)d_in[10];
    float* out = (float*)d_out;

    dim3 gp(S_ / 128, B_ * H_);
    proj_kernel<<<gp, 256>>>(queries, Wq, bq, 0);
    proj_kernel<<<gp, 256>>>(keys,    Wk, bk, 1);
    proj_kernel<<<gp, 256>>>(values,  Wv, bv, 2);

    dim3 ga(S_ / 64, B_ * H_);
    attn_kernel<<<ga, 128>>>();

    ln_kernel<<<B_ * S_, 256>>>(gamma, beta, out);
}

// round 2
// speedup vs baseline: 1.3660x; 1.3660x over previous
#include <cuda_runtime.h>
#include <stdint.h>
#include <math.h>

#define B_  2
#define S_  2048
#define D_  1024
#define H_  16
#define HD_ 64

// Scratch (allocation-free rule: __device__ globals)
__device__ float g_q[(size_t)B_ * H_ * S_ * HD_];
__device__ float g_k[(size_t)B_ * H_ * S_ * HD_];
__device__ float g_v[(size_t)B_ * H_ * S_ * HD_];
__device__ float g_att[(size_t)B_ * S_ * D_];

__device__ __forceinline__ uint32_t f2tf(float x) {
    uint32_t u;
    asm("cvt.rna.tf32.f32 %0, %1;" : "=r"(u) : "f"(x));
    return u;
}

__device__ __forceinline__ void mma_tf32(float* c, const uint32_t* a, uint32_t b0, uint32_t b1) {
    asm volatile(
        "mma.sync.aligned.m16n8k8.row.col.f32.tf32.tf32.f32 "
        "{%0,%1,%2,%3}, {%4,%5,%6,%7}, {%8,%9}, {%0,%1,%2,%3};"
        : "+f"(c[0]), "+f"(c[1]), "+f"(c[2]), "+f"(c[3])
        : "r"(a[0]), "r"(a[1]), "r"(a[2]), "r"(a[3]), "r"(b0), "r"(b1));
}

// ============================================================================
// Fused QKV projection: out[b,h,s,:] = X[b,s,:] @ W[h] + bias[h]
// grid = (S/128, B*H, 3). Block tile M=128 x N=64, 128 threads (4 warps),
// warp tile 64(M) x 32(N). Operands pre-converted to tf32 in smem.
// ============================================================================
__global__ __launch_bounds__(128) void proj_kernel(
    const float* __restrict__ Xq, const float* __restrict__ Xk, const float* __restrict__ Xv,
    const float* __restrict__ Wq, const float* __restrict__ Wk, const float* __restrict__ Wv,
    const float* __restrict__ bq, const float* __restrict__ bk, const float* __restrict__ bv)
{
    const int which = blockIdx.z;
    const float* X    = (which == 0) ? Xq : (which == 1) ? Xk : Xv;
    const float* W    = (which == 0) ? Wq : (which == 1) ? Wk : Wv;
    const float* bias = (which == 0) ? bq : (which == 1) ? bk : bv;
    float* out        = (which == 0) ? g_q : (which == 1) ? g_k : g_v;

    const int mt = blockIdx.x;           // 0..15  (S/128)
    const int bh = blockIdx.y;           // 0..31
    const int b  = bh >> 4;
    const int h  = bh & 15;

    const float* Xb = X    + (size_t)b * S_ * D_;
    const float* Wh = W    + (size_t)h * D_ * HD_;
    const float* bi = bias + (size_t)h * HD_;
    float*       Ob = out  + (size_t)bh * S_ * HD_;

    __shared__ uint32_t As[128][36];   // tf32 bits, [m][k]
    __shared__ uint32_t Bs[32][72];    // tf32 bits, [k][n] (stride 72: conflict-free b-frag reads)

    const int tid  = threadIdx.x;
    const int warp = tid >> 5;
    const int lane = tid & 31;
    const int g    = lane >> 2;
    const int t    = lane & 3;
    const int wm   = warp >> 1;     // 0..1 -> rows wm*64
    const int wn   = warp & 1;      // 0..1 -> cols wn*32

    float acc[4][4][4];
    #pragma unroll
    for (int ag = 0; ag < 4; ag++)
        #pragma unroll
        for (int j = 0; j < 4; j++)
            #pragma unroll
            for (int r = 0; r < 4; r++)
                acc[ag][j][r] = 0.0f;

    for (int k0 = 0; k0 < D_; k0 += 32) {
        // A tile: 128 x 32, coalesced float4, convert to tf32 on store
        {
            int r  = tid >> 3;            // 0..15
            int c4 = (tid & 7) * 4;       // 0..28
            #pragma unroll
            for (int i = 0; i < 8; i++) {
                float4 v = *(const float4*)&Xb[(size_t)(mt * 128 + r + i * 16) * D_ + k0 + c4];
                uint4 u = make_uint4(f2tf(v.x), f2tf(v.y), f2tf(v.z), f2tf(v.w));
                *(uint4*)&As[r + i * 16][c4] = u;
            }
        }
        // B tile: 32 x 64
        {
            int r  = tid >> 4;            // 0..7
            int c4 = (tid & 15) * 4;      // 0..60
            #pragma unroll
            for (int i = 0; i < 4; i++) {
                float4 v = *(const float4*)&Wh[(size_t)(k0 + r + i * 8) * HD_ + c4];
                uint4 u = make_uint4(f2tf(v.x), f2tf(v.y), f2tf(v.z), f2tf(v.w));
                *(uint4*)&Bs[r + i * 8][c4] = u;
            }
        }
        __syncthreads();

        #pragma unroll
        for (int kb = 0; kb < 4; kb++) {
            const int kk = kb * 8;
            uint32_t a[4][4];
            #pragma unroll
            for (int ag = 0; ag < 4; ag++) {
                int m = wm * 64 + ag * 16;
                a[ag][0] = As[m + g    ][kk + t    ];
                a[ag][1] = As[m + g + 8][kk + t    ];
                a[ag][2] = As[m + g    ][kk + t + 4];
                a[ag][3] = As[m + g + 8][kk + t + 4];
            }
            uint32_t bb[4][2];
            #pragma unroll
            for (int j = 0; j < 4; j++) {
                int n = wn * 32 + j * 8;
                bb[j][0] = Bs[kk + t    ][n + g];
                bb[j][1] = Bs[kk + t + 4][n + g];
            }
            #pragma unroll
            for (int ag = 0; ag < 4; ag++)
                #pragma unroll
                for (int j = 0; j < 4; j++)
                    mma_tf32(acc[ag][j], a[ag], bb[j][0], bb[j][1]);
        }
        __syncthreads();
    }

    // Epilogue: add bias, store float2
    #pragma unroll
    for (int ag = 0; ag < 4; ag++) {
        int row = mt * 128 + wm * 64 + ag * 16 + g;
        #pragma unroll
        for (int j = 0; j < 4; j++) {
            int col = wn * 32 + j * 8 + 2 * t;
            float b0 = bi[col], b1 = bi[col + 1];
            *(float2*)&Ob[(size_t)row * HD_ + col] =
                make_float2(acc[ag][j][0] + b0, acc[ag][j][1] + b1);
            *(float2*)&Ob[(size_t)(row + 8) * HD_ + col] =
                make_float2(acc[ag][j][2] + b0, acc[ag][j][3] + b1);
        }
    }
}

// ============================================================================
// Flash attention: one block = (b,h, 128-row Q tile). 128 threads (4 warps),
// each warp owns 32 q-rows (2 x 16-row mma groups). K/V in 32-key tiles.
// Q fragments live in registers as tf32 (pre-scaled by 1/sqrt(hd)).
// K/V/P stored in smem as tf32 bits (no cvt in inner loop).
// ============================================================================
__global__ __launch_bounds__(128) void attn_kernel()
{
    const int qt = blockIdx.x;          // 0..15 (S/128)
    const int bh = blockIdx.y;          // 0..31
    const int b  = bh >> 4;
    const int h  = bh & 15;
    const int q0 = qt * 128;

    const float* Qg = g_q + (size_t)bh * S_ * HD_;
    const float* Kg = g_k + (size_t)bh * S_ * HD_;
    const float* Vg = g_v + (size_t)bh * S_ * HD_;

    __shared__ uint32_t Ks[32][68];     // [key][d]  stride 68: K-frag reads conflict-free
    __shared__ uint32_t Vs[32][72];     // [key][d]  stride 72: V-frag reads conflict-free
    __shared__ uint32_t Ps[128][40];    // [row][key] stride 40: conflict-free both ways

    const int tid  = threadIdx.x;
    const int warp = tid >> 5;          // 0..3
    const int lane = tid & 31;
    const int g    = lane >> 2;
    const int t    = lane & 3;
    const int wrow = warp * 32;

    // Q fragments in registers, pre-scaled by 1/sqrt(64) = 0.125
    uint32_t q[2][8][4];
    #pragma unroll
    for (int grp = 0; grp < 2; grp++) {
        int r0 = q0 + wrow + grp * 16 + g;
        #pragma unroll
        for (int kb = 0; kb < 8; kb++) {
            int c = kb * 8 + t;
            q[grp][kb][0] = f2tf(Qg[(size_t)r0 * HD_ + c]           * 0.125f);
            q[grp][kb][1] = f2tf(Qg[(size_t)(r0 + 8) * HD_ + c]     * 0.125f);
            q[grp][kb][2] = f2tf(Qg[(size_t)r0 * HD_ + c + 4]       * 0.125f);
            q[grp][kb][3] = f2tf(Qg[(size_t)(r0 + 8) * HD_ + c + 4] * 0.125f);
        }
    }

    float o[2][8][4];
    #pragma unroll
    for (int grp = 0; grp < 2; grp++)
        #pragma unroll
        for (int j = 0; j < 8; j++)
            #pragma unroll
            for (int r = 0; r < 4; r++) o[grp][j][r] = 0.0f;
    float m[4] = {-INFINITY, -INFINITY, -INFINITY, -INFINITY};
    float l[4] = {0.0f, 0.0f, 0.0f, 0.0f};

    for (int kt = 0; kt < S_ / 32; kt++) {
        __syncthreads();   // prev iter done reading Ks/Vs
        // Load K/V tiles (32 x 64 each), convert to tf32 on store
        {
            int r  = tid >> 4;            // 0..7
            int c4 = (tid & 15) * 4;      // 0..60
            #pragma unroll
            for (int i = 0; i < 4; i++) {
                int rr = r + i * 8;
                size_t go = (size_t)(kt * 32 + rr) * HD_ + c4;
                float4 kv = *(const float4*)&Kg[go];
                float4 vv = *(const float4*)&Vg[go];
                *(uint4*)&Ks[rr][c4] = make_uint4(f2tf(kv.x), f2tf(kv.y), f2tf(kv.z), f2tf(kv.w));
                *(uint4*)&Vs[rr][c4] = make_uint4(f2tf(vv.x), f2tf(vv.y), f2tf(vv.z), f2tf(vv.w));
            }
        }
        __syncthreads();

        // S = (Q/8) K^T : 32 q-rows x 32 keys per warp (pre-scaled)
        float s[2][4][4];
        #pragma unroll
        for (int grp = 0; grp < 2; grp++)
            #pragma unroll
            for (int j = 0; j < 4; j++)
                #pragma unroll
                for (int r = 0; r < 4; r++) s[grp][j][r] = 0.0f;

        #pragma unroll
        for (int kb = 0; kb < 8; kb++) {
            const int kk = kb * 8;
            uint32_t bk_[4][2];
            #pragma unroll
            for (int j = 0; j < 4; j++) {
                bk_[j][0] = Ks[j * 8 + g][kk + t    ];
                bk_[j][1] = Ks[j * 8 + g][kk + t + 4];
            }
            #pragma unroll
            for (int grp = 0; grp < 2; grp++)
                #pragma unroll
                for (int j = 0; j < 4; j++)
                    mma_tf32(s[grp][j], q[grp][kb], bk_[j][0], bk_[j][1]);
        }

        // Online softmax per 16-row group (stats warp-local via t-lane shuffles)
        #pragma unroll
        for (int grp = 0; grp < 2; grp++) {
            const int i0 = grp * 2, i1 = grp * 2 + 1;
            float mx0 = -INFINITY, mx1 = -INFINITY;
            #pragma unroll
            for (int j = 0; j < 4; j++) {
                mx0 = fmaxf(mx0, fmaxf(s[grp][j][0], s[grp][j][1]));
                mx1 = fmaxf(mx1, fmaxf(s[grp][j][2], s[grp][j][3]));
            }
            mx0 = fmaxf(mx0, __shfl_xor_sync(0xffffffff, mx0, 1));
            mx0 = fmaxf(mx0, __shfl_xor_sync(0xffffffff, mx0, 2));
            mx1 = fmaxf(mx1, __shfl_xor_sync(0xffffffff, mx1, 1));
            mx1 = fmaxf(mx1, __shfl_xor_sync(0xffffffff, mx1, 2));

            float mn0 = fmaxf(m[i0], mx0), mn1 = fmaxf(m[i1], mx1);
            float al0 = __expf(m[i0] - mn0), al1 = __expf(m[i1] - mn1);
            m[i0] = mn0; m[i1] = mn1;

            float sum0 = 0.0f, sum1 = 0.0f;
            int rp = wrow + grp * 16 + g;
            #pragma unroll
            for (int j = 0; j < 4; j++) {
                float p00 = __expf(s[grp][j][0] - mn0);
                float p01 = __expf(s[grp][j][1] - mn0);
                float p10 = __expf(s[grp][j][2] - mn1);
                float p11 = __expf(s[grp][j][3] - mn1);
                sum0 += p00 + p01;
                sum1 += p10 + p11;
                *(uint2*)&Ps[rp    ][j * 8 + 2 * t] = make_uint2(f2tf(p00), f2tf(p01));
                *(uint2*)&Ps[rp + 8][j * 8 + 2 * t] = make_uint2(f2tf(p10), f2tf(p11));
            }
            sum0 += __shfl_xor_sync(0xffffffff, sum0, 1);
            sum0 += __shfl_xor_sync(0xffffffff, sum0, 2);
            sum1 += __shfl_xor_sync(0xffffffff, sum1, 1);
            sum1 += __shfl_xor_sync(0xffffffff, sum1, 2);
            l[i0] = l[i0] * al0 + sum0;
            l[i1] = l[i1] * al1 + sum1;

            #pragma unroll
            for (int j = 0; j < 8; j++) {
                o[grp][j][0] *= al0; o[grp][j][1] *= al0;
                o[grp][j][2] *= al1; o[grp][j][3] *= al1;
            }
        }
        __syncwarp();   // Ps rows are warp-private; order writes before reads

        // O += P V  (32 keys, N = 64 head dims)
        #pragma unroll
        for (int kb = 0; kb < 4; kb++) {
            const int kk = kb * 8;
            uint32_t a0[4], a1[4];
            {
                int rp = wrow + g;
                a0[0] = Ps[rp    ][kk + t    ];
                a0[1] = Ps[rp + 8][kk + t    ];
                a0[2] = Ps[rp    ][kk + t + 4];
                a0[3] = Ps[rp + 8][kk + t + 4];
                rp = wrow + 16 + g;
                a1[0] = Ps[rp    ][kk + t    ];
                a1[1] = Ps[rp + 8][kk + t    ];
                a1[2] = Ps[rp    ][kk + t + 4];
                a1[3] = Ps[rp + 8][kk + t + 4];
            }
            #pragma unroll
            for (int j = 0; j < 8; j++) {
                uint32_t b0 = Vs[kk + t    ][j * 8 + g];
                uint32_t b1 = Vs[kk + t + 4][j * 8 + g];
                mma_tf32(o[0][j], a0, b0, b1);
                mma_tf32(o[1][j], a1, b0, b1);
            }
        }
    }

    // Epilogue: normalize, scatter into [B,S,D] (concat heads)
    float inv[4] = {1.0f / l[0], 1.0f / l[1], 1.0f / l[2], 1.0f / l[3]};
    #pragma unroll
    for (int grp = 0; grp < 2; grp++) {
        #pragma unroll
        for (int j = 0; j < 8; j++) {
            int srow = q0 + wrow + grp * 16 + g;
            int col  = h * HD_ + j * 8 + 2 * t;
            *(float2*)&g_att[((size_t)b * S_ + srow) * D_ + col] =
                make_float2(o[grp][j][0] * inv[grp * 2], o[grp][j][1] * inv[grp * 2]);
            *(float2*)&g_att[((size_t)b * S_ + srow + 8) * D_ + col] =
                make_float2(o[grp][j][2] * inv[grp * 2 + 1], o[grp][j][3] * inv[grp * 2 + 1]);
        }
    }
}

// ============================================================================
// LayerNorm over last dim (1024). One block (256 thr) per row; float4 I/O.
// ============================================================================
__global__ __launch_bounds__(256) void ln_kernel(const float* __restrict__ gamma,
                                                 const float* __restrict__ beta,
                                                 float* __restrict__ out)
{
    const int row = blockIdx.x;
    const float* x = g_att + (size_t)row * D_;
    float*       y = out   + (size_t)row * D_;

    const int tid = threadIdx.x;
    float4 v = *(const float4*)&x[tid * 4];
    float sum = v.x + v.y + v.z + v.w;
    float sq  = v.x * v.x + v.y * v.y + v.z * v.z + v.w * v.w;

    #pragma unroll
    for (int off = 16; off > 0; off >>= 1) {
        sum += __shfl_down_sync(0xffffffff, sum, off);
        sq  += __shfl_down_sync(0xffffffff, sq,  off);
    }
    __shared__ float rs[8], rq[8], stats[2];
    int warp = tid >> 5, lane = tid & 31;
    if (lane == 0) { rs[warp] = sum; rq[warp] = sq; }
    __syncthreads();
    if (tid == 0) {
        float ts = 0.0f, tq = 0.0f;
        #pragma unroll
        for (int i = 0; i < 8; i++) { ts += rs[i]; tq += rq[i]; }
        float mean = ts * (1.0f / D_);
        float var  = tq * (1.0f / D_) - mean * mean;
        stats[0] = mean;
        stats[1] = rsqrtf(var + 1e-5f);
    }
    __syncthreads();
    float mean = stats[0], rstd = stats[1];

    float4 gm = *(const float4*)&gamma[tid * 4];
    float4 bt = *(const float4*)&beta[tid * 4];
    float4 r;
    r.x = (v.x - mean) * rstd * gm.x + bt.x;
    r.y = (v.y - mean) * rstd * gm.y + bt.y;
    r.z = (v.z - mean) * rstd * gm.z + bt.z;
    r.w = (v.w - mean) * rstd * gm.w + bt.w;
    *(float4*)&y[tid * 4] = r;
}

extern "C" void kernel_launch(void* const* d_in, const int* in_sizes, int n_in,
                              void* d_out, int out_size)
{
    (void)in_sizes; (void)n_in; (void)out_size;
    const float* queries = (const float*)d_in[0];
    const float* keys    = (const float*)d_in[1];
    const float* values  = (const float*)d_in[2];
    const float* Wq      = (const float*)d_in[3];
    const float* bq      = (const float*)d_in[4];
    const float* Wk      = (const float*)d_in[5];
    const float* bk      = (const float*)d_in[6];
    const float* Wv      = (const float*)d_in[7];
    const float* bv      = (const float*)d_in[8];
    const float* gamma   = (const float*)d_in[9];
    const float* beta    = (const float*)d_in[10];
    float* out = (float*)d_out;

    dim3 gp(S_ / 128, B_ * H_, 3);
    proj_kernel<<<gp, 128>>>(queries, keys, values, Wq, Wk, Wv, bq, bk, bv);

    dim3 ga(S_ / 128, B_ * H_);
    attn_kernel<<<ga, 128>>>();

    ln_kernel<<<B_ * S_, 256>>>(gamma, beta, out);
}

// round 3
// speedup vs baseline: 1.4431x; 1.0564x over previous
#include <cuda_runtime.h>
#include <stdint.h>
#include <math.h>

#define B_  2
#define S_  2048
#define D_  1024
#define H_  16
#define HD_ 64

// Scratch (allocation-free rule: __device__ globals). q/k/v hold tf32-rounded
// bit patterns (q additionally pre-scaled by 1/sqrt(HD)).
__device__ float g_q[(size_t)B_ * H_ * S_ * HD_];
__device__ float g_k[(size_t)B_ * H_ * S_ * HD_];
__device__ float g_v[(size_t)B_ * H_ * S_ * HD_];
__device__ float g_att[(size_t)B_ * S_ * D_];

__device__ __forceinline__ uint32_t f2tf(float x) {
    uint32_t u;
    asm("cvt.rna.tf32.f32 %0, %1;" : "=r"(u) : "f"(x));
    return u;
}

__device__ __forceinline__ void mma_tf32(float* c, const uint32_t* a, uint32_t b0, uint32_t b1) {
    asm volatile(
        "mma.sync.aligned.m16n8k8.row.col.f32.tf32.tf32.f32 "
        "{%0,%1,%2,%3}, {%4,%5,%6,%7}, {%8,%9}, {%0,%1,%2,%3};"
        : "+f"(c[0]), "+f"(c[1]), "+f"(c[2]), "+f"(c[3])
        : "r"(a[0]), "r"(a[1]), "r"(a[2]), "r"(a[3]), "r"(b0), "r"(b1));
}

#define CP_ASYNC16(saddr, gptr) \
    asm volatile("cp.async.cg.shared.global [%0], [%1], 16;\n" :: "r"(saddr), "l"(gptr))
#define CP_COMMIT() asm volatile("cp.async.commit_group;\n" ::: "memory")
#define CP_WAIT0()  asm volatile("cp.async.wait_group 0;\n" ::: "memory")

// ============================================================================
// Fused QKV projection: out[b,h,s,:] = tf32(X[b,s,:] @ W[h] + bias[h])
// grid = (S/128, B*(H/2), 3). Block tile M=128 x N=128 (TWO heads per block),
// 256 threads (8 warps, 2Mx4N), warp tile 64x32. tf32 operands in smem.
// Epilogue stores tf32-rounded bits; Q pre-scaled by 1/sqrt(HD).
// ============================================================================
__global__ __launch_bounds__(256) void proj_kernel(
    const float* __restrict__ Xq, const float* __restrict__ Xk, const float* __restrict__ Xv,
    const float* __restrict__ Wq, const float* __restrict__ Wk, const float* __restrict__ Wv,
    const float* __restrict__ bq, const float* __restrict__ bk, const float* __restrict__ bv)
{
    const int which = blockIdx.z;
    const float* X    = (which == 0) ? Xq : (which == 1) ? Xk : Xv;
    const float* W    = (which == 0) ? Wq : (which == 1) ? Wk : Wv;
    const float* bias = (which == 0) ? bq : (which == 1) ? bk : bv;
    float* out        = (which == 0) ? g_q : (which == 1) ? g_k : g_v;
    const float sc    = (which == 0) ? 0.125f : 1.0f;

    const int mt = blockIdx.x;           // 0..15  (S/128)
    const int bp = blockIdx.y;           // 0..15  (B * H/2)
    const int b  = bp >> 3;
    const int h0 = (bp & 7) * 2;         // first of two heads

    const float* Xb = X + (size_t)b * S_ * D_;

    __shared__ uint32_t As[128][36];     // tf32 bits, [m][k]
    __shared__ uint32_t Bs[32][136];     // tf32 bits, [k][n], stride 136 (≡8 mod 32)

    const int tid  = threadIdx.x;
    const int warp = tid >> 5;
    const int lane = tid & 31;
    const int g    = lane >> 2;
    const int t    = lane & 3;
    const int wm   = warp >> 2;          // 0..1 -> rows wm*64
    const int wn   = warp & 3;           // 0..3 -> cols wn*32

    float acc[4][4][4];
    #pragma unroll
    for (int ag = 0; ag < 4; ag++)
        #pragma unroll
        for (int j = 0; j < 4; j++)
            #pragma unroll
            for (int r = 0; r < 4; r++)
                acc[ag][j][r] = 0.0f;

    for (int k0 = 0; k0 < D_; k0 += 32) {
        // A tile: 128 x 32
        {
            int r  = tid >> 3;            // 0..31
            int c4 = (tid & 7) * 4;       // 0..28
            #pragma unroll
            for (int i = 0; i < 4; i++) {
                float4 v = *(const float4*)&Xb[(size_t)(mt * 128 + r + i * 32) * D_ + k0 + c4];
                *(uint4*)&As[r + i * 32][c4] =
                    make_uint4(f2tf(v.x), f2tf(v.y), f2tf(v.z), f2tf(v.w));
            }
        }
        // B tile: 32 x 128 (two heads side by side)
        {
            int r = tid >> 3;             // 0..31 (k row)
            #pragma unroll
            for (int i = 0; i < 4; i++) {
                int c = i * 32 + (tid & 7) * 4;          // 0..124
                int h = h0 + (c >> 6);
                int ck = c & 63;
                float4 v = *(const float4*)&W[((size_t)h * D_ + k0 + r) * HD_ + ck];
                *(uint4*)&Bs[r][c] =
                    make_uint4(f2tf(v.x), f2tf(v.y), f2tf(v.z), f2tf(v.w));
            }
        }
        __syncthreads();

        #pragma unroll
        for (int kb = 0; kb < 4; kb++) {
            const int kk = kb * 8;
            uint32_t a[4][4];
            #pragma unroll
            for (int ag = 0; ag < 4; ag++) {
                int m = wm * 64 + ag * 16;
                a[ag][0] = As[m + g    ][kk + t    ];
                a[ag][1] = As[m + g + 8][kk + t    ];
                a[ag][2] = As[m + g    ][kk + t + 4];
                a[ag][3] = As[m + g + 8][kk + t + 4];
            }
            uint32_t bb[4][2];
            #pragma unroll
            for (int j = 0; j < 4; j++) {
                int n = wn * 32 + j * 8;
                bb[j][0] = Bs[kk + t    ][n + g];
                bb[j][1] = Bs[kk + t + 4][n + g];
            }
            #pragma unroll
            for (int ag = 0; ag < 4; ag++)
                #pragma unroll
                for (int j = 0; j < 4; j++)
                    mma_tf32(acc[ag][j], a[ag], bb[j][0], bb[j][1]);
        }
        __syncthreads();
    }

    // Epilogue: add bias, scale, round to tf32, store
    #pragma unroll
    for (int ag = 0; ag < 4; ag++) {
        int row = mt * 128 + wm * 64 + ag * 16 + g;
        #pragma unroll
        for (int j = 0; j < 4; j++) {
            int col = wn * 32 + j * 8 + 2 * t;           // 0..126 (even)
            int h   = h0 + (col >> 6);
            int ck  = col & 63;
            const float* bi = bias + (size_t)h * HD_;
            float b0 = bi[ck], b1 = bi[ck + 1];
            float* Ob = out + (size_t)(b * H_ + h) * S_ * HD_;
            uint2 v0 = make_uint2(f2tf((acc[ag][j][0] + b0) * sc),
                                  f2tf((acc[ag][j][1] + b1) * sc));
            uint2 v1 = make_uint2(f2tf((acc[ag][j][2] + b0) * sc),
                                  f2tf((acc[ag][j][3] + b1) * sc));
            *(uint2*)&Ob[(size_t)row * HD_ + ck]       = v0;
            *(uint2*)&Ob[(size_t)(row + 8) * HD_ + ck] = v1;
        }
    }
}

// ============================================================================
// Flash attention: one block = (b,h, 128-row Q tile). 128 threads (4 warps),
// warp owns 32 q-rows. K/V tiles (32 keys) double-buffered via cp.async
// (gmem already tf32 bits -> zero cvt in the loop). Q frags in registers.
// Dynamic smem 54272 B.
// ============================================================================
#define KS_TILE 2176            // 32*68 words
#define VS_TILE 2304            // 32*72 words
#define KS_OFF  0
#define VS_OFF  (2 * KS_TILE)                   // 4352
#define PS_OFF  (VS_OFF + 2 * VS_TILE)          // 8960
#define ATTN_SMEM_WORDS (PS_OFF + 128 * 36)     // 13568
#define ATTN_SMEM_BYTES (ATTN_SMEM_WORDS * 4)   // 54272

__global__ __launch_bounds__(128) void attn_kernel()
{
    extern __shared__ uint32_t dyn[];

    const int qt = blockIdx.x;          // 0..15 (S/128)
    const int bh = blockIdx.y;          // 0..31
    const int b  = bh >> 4;
    const int h  = bh & 15;
    const int q0 = qt * 128;

    const float* Qg = g_q + (size_t)bh * S_ * HD_;
    const float* Kg = g_k + (size_t)bh * S_ * HD_;
    const float* Vg = g_v + (size_t)bh * S_ * HD_;
    const uint32_t* Qu = (const uint32_t*)Qg;

    uint32_t* Ps = dyn + PS_OFF;        // [128][36]

    const int tid  = threadIdx.x;
    const int warp = tid >> 5;          // 0..3
    const int lane = tid & 31;
    const int g    = lane >> 2;
    const int t    = lane & 3;
    const int wrow = warp * 32;

    const uint32_t sbase = (uint32_t)__cvta_generic_to_shared(dyn);
    const int ldr  = tid >> 4;          // 0..7
    const int ldc4 = (tid & 15) * 4;    // 0..60

    // Q fragments (already tf32 + pre-scaled in gmem)
    uint32_t q[2][8][4];
    #pragma unroll
    for (int grp = 0; grp < 2; grp++) {
        int r0 = q0 + wrow + grp * 16 + g;
        #pragma unroll
        for (int kb = 0; kb < 8; kb++) {
            int c = kb * 8 + t;
            q[grp][kb][0] = Qu[(size_t)r0 * HD_ + c];
            q[grp][kb][1] = Qu[(size_t)(r0 + 8) * HD_ + c];
            q[grp][kb][2] = Qu[(size_t)r0 * HD_ + c + 4];
            q[grp][kb][3] = Qu[(size_t)(r0 + 8) * HD_ + c + 4];
        }
    }

    float o[2][8][4];
    #pragma unroll
    for (int grp = 0; grp < 2; grp++)
        #pragma unroll
        for (int j = 0; j < 8; j++)
            #pragma unroll
            for (int r = 0; r < 4; r++) o[grp][j][r] = 0.0f;
    float m[4] = {-INFINITY, -INFINITY, -INFINITY, -INFINITY};
    float l[4] = {0.0f, 0.0f, 0.0f, 0.0f};

    // Prologue: prefetch tile 0 into buffer 0
    {
        #pragma unroll
        for (int i = 0; i < 4; i++) {
            int rr = ldr + i * 8;
            CP_ASYNC16(sbase + (KS_OFF + rr * 68 + ldc4) * 4, Kg + (size_t)rr * HD_ + ldc4);
            CP_ASYNC16(sbase + (VS_OFF + rr * 72 + ldc4) * 4, Vg + (size_t)rr * HD_ + ldc4);
        }
        CP_COMMIT();
    }

    const int NT = S_ / 32;
    for (int kt = 0; kt < NT; kt++) {
        const int buf = kt & 1;
        CP_WAIT0();
        __syncthreads();                // all warps done with buf^1 from kt-1

        if (kt + 1 < NT) {              // prefetch next tile into buf^1
            const int nb = buf ^ 1;
            #pragma unroll
            for (int i = 0; i < 4; i++) {
                int rr = ldr + i * 8;
                size_t go = (size_t)((kt + 1) * 32 + rr) * HD_ + ldc4;
                CP_ASYNC16(sbase + (KS_OFF + nb * KS_TILE + rr * 68 + ldc4) * 4, Kg + go);
                CP_ASYNC16(sbase + (VS_OFF + nb * VS_TILE + rr * 72 + ldc4) * 4, Vg + go);
            }
        }
        CP_COMMIT();

        const uint32_t* KsB = dyn + KS_OFF + buf * KS_TILE;   // [32][68]
        const uint32_t* VsB = dyn + VS_OFF + buf * VS_TILE;   // [32][72]

        // S = Q K^T : 32 q-rows x 32 keys per warp
        float s[2][4][4];
        #pragma unroll
        for (int grp = 0; grp < 2; grp++)
            #pragma unroll
            for (int j = 0; j < 4; j++)
                #pragma unroll
                for (int r = 0; r < 4; r++) s[grp][j][r] = 0.0f;

        #pragma unroll
        for (int kb = 0; kb < 8; kb++) {
            const int kk = kb * 8;
            uint32_t bk_[4][2];
            #pragma unroll
            for (int j = 0; j < 4; j++) {
                bk_[j][0] = KsB[(j * 8 + g) * 68 + kk + t    ];
                bk_[j][1] = KsB[(j * 8 + g) * 68 + kk + t + 4];
            }
            #pragma unroll
            for (int grp = 0; grp < 2; grp++)
                #pragma unroll
                for (int j = 0; j < 4; j++)
                    mma_tf32(s[grp][j], q[grp][kb], bk_[j][0], bk_[j][1]);
        }

        // Online softmax per 16-row group
        #pragma unroll
        for (int grp = 0; grp < 2; grp++) {
            const int i0 = grp * 2, i1 = grp * 2 + 1;
            float mx0 = -INFINITY, mx1 = -INFINITY;
            #pragma unroll
            for (int j = 0; j < 4; j++) {
                mx0 = fmaxf(mx0, fmaxf(s[grp][j][0], s[grp][j][1]));
                mx1 = fmaxf(mx1, fmaxf(s[grp][j][2], s[grp][j][3]));
            }
            mx0 = fmaxf(mx0, __shfl_xor_sync(0xffffffff, mx0, 1));
            mx0 = fmaxf(mx0, __shfl_xor_sync(0xffffffff, mx0, 2));
            mx1 = fmaxf(mx1, __shfl_xor_sync(0xffffffff, mx1, 1));
            mx1 = fmaxf(mx1, __shfl_xor_sync(0xffffffff, mx1, 2));

            float mn0 = fmaxf(m[i0], mx0), mn1 = fmaxf(m[i1], mx1);
            float al0 = __expf(m[i0] - mn0), al1 = __expf(m[i1] - mn1);
            m[i0] = mn0; m[i1] = mn1;

            float sum0 = 0.0f, sum1 = 0.0f;
            int rp = wrow + grp * 16 + g;
            #pragma unroll
            for (int j = 0; j < 4; j++) {
                float p00 = __expf(s[grp][j][0] - mn0);
                float p01 = __expf(s[grp][j][1] - mn0);
                float p10 = __expf(s[grp][j][2] - mn1);
                float p11 = __expf(s[grp][j][3] - mn1);
                sum0 += p00 + p01;
                sum1 += p10 + p11;
                *(uint2*)&Ps[rp * 36 + j * 8 + 2 * t]       = make_uint2(f2tf(p00), f2tf(p01));
                *(uint2*)&Ps[(rp + 8) * 36 + j * 8 + 2 * t] = make_uint2(f2tf(p10), f2tf(p11));
            }
            sum0 += __shfl_xor_sync(0xffffffff, sum0, 1);
            sum0 += __shfl_xor_sync(0xffffffff, sum0, 2);
            sum1 += __shfl_xor_sync(0xffffffff, sum1, 1);
            sum1 += __shfl_xor_sync(0xffffffff, sum1, 2);
            l[i0] = l[i0] * al0 + sum0;
            l[i1] = l[i1] * al1 + sum1;

            #pragma unroll
            for (int j = 0; j < 8; j++) {
                o[grp][j][0] *= al0; o[grp][j][1] *= al0;
                o[grp][j][2] *= al1; o[grp][j][3] *= al1;
            }
        }
        __syncwarp();   // Ps rows are warp-private; order writes before reads

        // O += P V
        #pragma unroll
        for (int kb = 0; kb < 4; kb++) {
            const int kk = kb * 8;
            uint32_t a0[4], a1[4];
            {
                int rp = wrow + g;
                a0[0] = Ps[rp * 36 + kk + t    ];
                a0[1] = Ps[(rp + 8) * 36 + kk + t    ];
                a0[2] = Ps[rp * 36 + kk + t + 4];
                a0[3] = Ps[(rp + 8) * 36 + kk + t + 4];
                rp = wrow + 16 + g;
                a1[0] = Ps[rp * 36 + kk + t    ];
                a1[1] = Ps[(rp + 8) * 36 + kk + t    ];
                a1[2] = Ps[rp * 36 + kk + t + 4];
                a1[3] = Ps[(rp + 8) * 36 + kk + t + 4];
            }
            #pragma unroll
            for (int j = 0; j < 8; j++) {
                uint32_t b0 = VsB[(kk + t) * 72 + j * 8 + g];
                uint32_t b1 = VsB[(kk + t + 4) * 72 + j * 8 + g];
                mma_tf32(o[0][j], a0, b0, b1);
                mma_tf32(o[1][j], a1, b0, b1);
            }
        }
    }

    // Epilogue: normalize, scatter into [B,S,D] (concat heads)
    float inv[4] = {1.0f / l[0], 1.0f / l[1], 1.0f / l[2], 1.0f / l[3]};
    #pragma unroll
    for (int grp = 0; grp < 2; grp++) {
        #pragma unroll
        for (int j = 0; j < 8; j++) {
            int srow = q0 + wrow + grp * 16 + g;
            int col  = h * HD_ + j * 8 + 2 * t;
            *(float2*)&g_att[((size_t)b * S_ + srow) * D_ + col] =
                make_float2(o[grp][j][0] * inv[grp * 2], o[grp][j][1] * inv[grp * 2]);
            *(float2*)&g_att[((size_t)b * S_ + srow + 8) * D_ + col] =
                make_float2(o[grp][j][2] * inv[grp * 2 + 1], o[grp][j][3] * inv[grp * 2 + 1]);
        }
    }
}

// ============================================================================
// LayerNorm over last dim (1024). One block (256 thr) per row; float4 I/O.
// ============================================================================
__global__ __launch_bounds__(256) void ln_kernel(const float* __restrict__ gamma,
                                                 const float* __restrict__ beta,
                                                 float* __restrict__ out)
{
    const int row = blockIdx.x;
    const float* x = g_att + (size_t)row * D_;
    float*       y = out   + (size_t)row * D_;

    const int tid = threadIdx.x;
    float4 v = *(const float4*)&x[tid * 4];
    float sum = v.x + v.y + v.z + v.w;
    float sq  = v.x * v.x + v.y * v.y + v.z * v.z + v.w * v.w;

    #pragma unroll
    for (int off = 16; off > 0; off >>= 1) {
        sum += __shfl_down_sync(0xffffffff, sum, off);
        sq  += __shfl_down_sync(0xffffffff, sq,  off);
    }
    __shared__ float rs[8], rq[8], stats[2];
    int warp = tid >> 5, lane = tid & 31;
    if (lane == 0) { rs[warp] = sum; rq[warp] = sq; }
    __syncthreads();
    if (tid == 0) {
        float ts = 0.0f, tq = 0.0f;
        #pragma unroll
        for (int i = 0; i < 8; i++) { ts += rs[i]; tq += rq[i]; }
        float mean = ts * (1.0f / D_);
        float var  = tq * (1.0f / D_) - mean * mean;
        stats[0] = mean;
        stats[1] = rsqrtf(var + 1e-5f);
    }
    __syncthreads();
    float mean = stats[0], rstd = stats[1];

    float4 gm = *(const float4*)&gamma[tid * 4];
    float4 bt = *(const float4*)&beta[tid * 4];
    float4 r;
    r.x = (v.x - mean) * rstd * gm.x + bt.x;
    r.y = (v.y - mean) * rstd * gm.y + bt.y;
    r.z = (v.z - mean) * rstd * gm.z + bt.z;
    r.w = (v.w - mean) * rstd * gm.w + bt.w;
    *(float4*)&y[tid * 4] = r;
}

extern "C" void kernel_launch(void* const* d_in, const int* in_sizes, int n_in,
                              void* d_out, int out_size)
{
    (void)in_sizes; (void)n_in; (void)out_size;
    const float* queries = (const float*)d_in[0];
    const float* keys    = (const float*)d_in[1];
    const float* values  = (const float*)d_in[2];
    const float* Wq      = (const float*)d_in[3];
    const float* bq      = (const float*)d_in[4];
    const float* Wk      = (const float*)d_in[5];
    const float* bk      = (const float*)d_in[6];
    const float* Wv      = (const float*)d_in[7];
    const float* bv      = (const float*)d_in[8];
    const float* gamma   = (const float*)d_in[9];
    const float* beta    = (const float*)d_in[10];
    float* out = (float*)d_out;

    // Host-side module attribute (idempotent; first set happens on the
    // uncaptured correctness call and persists).
    (void)cudaFuncSetAttribute(attn_kernel,
                               cudaFuncAttributeMaxDynamicSharedMemorySize,
                               ATTN_SMEM_BYTES);

    dim3 gp(S_ / 128, B_ * H_ / 2, 3);
    proj_kernel<<<gp, 256>>>(queries, keys, values, Wq, Wk, Wv, bq, bk, bv);

    dim3 ga(S_ / 128, B_ * H_);
    attn_kernel<<<ga, 128, ATTN_SMEM_BYTES>>>();

    ln_kernel<<<B_ * S_, 256>>>(gamma, beta, out);
}

// round 4
// speedup vs baseline: 1.4928x; 1.0345x over previous
#include <cuda_runtime.h>
#include <stdint.h>
#include <math.h>

#define B_  2
#define S_  2048
#define D_  1024
#define H_  16
#define HD_ 64

// Scratch (allocation-free rule: __device__ globals). q/k/v hold tf32-rounded
// bit patterns (q additionally pre-scaled by 1/sqrt(HD)).
__device__ float g_q[(size_t)B_ * H_ * S_ * HD_];
__device__ float g_k[(size_t)B_ * H_ * S_ * HD_];
__device__ float g_v[(size_t)B_ * H_ * S_ * HD_];
__device__ float g_att[(size_t)B_ * S_ * D_];

__device__ __forceinline__ uint32_t f2tf(float x) {
    uint32_t u;
    asm("cvt.rna.tf32.f32 %0, %1;" : "=r"(u) : "f"(x));
    return u;
}

__device__ __forceinline__ void mma_tf32(float* c, const uint32_t* a, uint32_t b0, uint32_t b1) {
    asm volatile(
        "mma.sync.aligned.m16n8k8.row.col.f32.tf32.tf32.f32 "
        "{%0,%1,%2,%3}, {%4,%5,%6,%7}, {%8,%9}, {%0,%1,%2,%3};"
        : "+f"(c[0]), "+f"(c[1]), "+f"(c[2]), "+f"(c[3])
        : "r"(a[0]), "r"(a[1]), "r"(a[2]), "r"(a[3]), "r"(b0), "r"(b1));
}

#define CP_ASYNC16(saddr, gptr) \
    asm volatile("cp.async.cg.shared.global [%0], [%1], 16;\n" :: "r"(saddr), "l"(gptr))
#define CP_COMMIT() asm volatile("cp.async.commit_group;\n" ::: "memory")
#define CP_WAIT0()  asm volatile("cp.async.wait_group 0;\n" ::: "memory")

// ============================================================================
// Fused QKV projection: out[b,h,s,:] = tf32(X[b,s,:] @ W[h] + bias[h])
// grid = (S/128, B*(H/2), 3). Block tile M=128 x N=128 (two heads per block),
// 256 threads (8 warps, 2Mx4N), warp tile 64x32.
// cp.async 2-stage pipeline; raw fp32 bits fed to mma.tf32 (HW truncation).
// Dynamic smem: 2*(128*36 + 32*136) words = 71680 B.
// ============================================================================
#define PA_TILE (128 * 36)
#define PB_TILE (32 * 136)
#define PA_OFF  0
#define PB_OFF  (2 * PA_TILE)
#define PROJ_SMEM_WORDS (PB_OFF + 2 * PB_TILE)
#define PROJ_SMEM_BYTES (PROJ_SMEM_WORDS * 4)

__global__ __launch_bounds__(256) void proj_kernel(
    const float* __restrict__ Xq, const float* __restrict__ Xk, const float* __restrict__ Xv,
    const float* __restrict__ Wq, const float* __restrict__ Wk, const float* __restrict__ Wv,
    const float* __restrict__ bq, const float* __restrict__ bk, const float* __restrict__ bv)
{
    extern __shared__ uint32_t dyn[];

    const int which = blockIdx.z;
    const float* X    = (which == 0) ? Xq : (which == 1) ? Xk : Xv;
    const float* W    = (which == 0) ? Wq : (which == 1) ? Wk : Wv;
    const float* bias = (which == 0) ? bq : (which == 1) ? bk : bv;
    float* out        = (which == 0) ? g_q : (which == 1) ? g_k : g_v;
    const float sc    = (which == 0) ? 0.125f : 1.0f;

    const int mt = blockIdx.x;           // 0..15  (S/128)
    const int bp = blockIdx.y;           // 0..15  (B * H/2)
    const int b  = bp >> 3;
    const int h0 = (bp & 7) * 2;         // first of two heads

    const float* Xb = X + (size_t)b * S_ * D_;

    const int tid  = threadIdx.x;
    const int warp = tid >> 5;
    const int lane = tid & 31;
    const int g    = lane >> 2;
    const int t    = lane & 3;
    const int wm   = warp >> 2;          // 0..1 -> rows wm*64
    const int wn   = warp & 3;           // 0..3 -> cols wn*32

    const uint32_t sbase = (uint32_t)__cvta_generic_to_shared(dyn);

    // Loader indices
    const int ar  = tid >> 3;            // 0..31 (A row base, +i*32)
    const int ac4 = (tid & 7) * 4;       // 0..28
    const int br  = tid >> 3;            // 0..31 (B k-row)

    float acc[4][4][4];
    #pragma unroll
    for (int ag = 0; ag < 4; ag++)
        #pragma unroll
        for (int j = 0; j < 4; j++)
            #pragma unroll
            for (int r = 0; r < 4; r++)
                acc[ag][j][r] = 0.0f;

    // Issue loads for one k-chunk into buffer `buf`
    auto issue_stage = [&](int k0, int buf) {
        // A tile: 128 x 32 floats
        uint32_t adst = sbase + (PA_OFF + buf * PA_TILE) * 4;
        #pragma unroll
        for (int i = 0; i < 4; i++) {
            int row = ar + i * 32;
            CP_ASYNC16(adst + (row * 36 + ac4) * 4,
                       Xb + (size_t)(mt * 128 + row) * D_ + k0 + ac4);
        }
        // B tile: 32 x 128 floats (two heads side by side)
        uint32_t bdst = sbase + (PB_OFF + buf * PB_TILE) * 4;
        #pragma unroll
        for (int i = 0; i < 4; i++) {
            int c  = i * 32 + (tid & 7) * 4;     // 0..124
            int h  = h0 + (c >> 6);
            int ck = c & 63;
            CP_ASYNC16(bdst + (br * 136 + c) * 4,
                       W + ((size_t)h * D_ + k0 + br) * HD_ + ck);
        }
        CP_COMMIT();
    };

    issue_stage(0, 0);

    const int NK = D_ / 32;
    for (int kc = 0; kc < NK; kc++) {
        const int buf = kc & 1;
        CP_WAIT0();
        __syncthreads();                 // stage ready; everyone done with buf^1

        if (kc + 1 < NK) issue_stage((kc + 1) * 32, buf ^ 1);

        const uint32_t* As = dyn + PA_OFF + buf * PA_TILE;   // [128][36]
        const uint32_t* Bs = dyn + PB_OFF + buf * PB_TILE;   // [32][136]

        #pragma unroll
        for (int kb = 0; kb < 4; kb++) {
            const int kk = kb * 8;
            uint32_t a[4][4];
            #pragma unroll
            for (int ag = 0; ag < 4; ag++) {
                int m = wm * 64 + ag * 16;
                a[ag][0] = As[(m + g    ) * 36 + kk + t    ];
                a[ag][1] = As[(m + g + 8) * 36 + kk + t    ];
                a[ag][2] = As[(m + g    ) * 36 + kk + t + 4];
                a[ag][3] = As[(m + g + 8) * 36 + kk + t + 4];
            }
            uint32_t bb[4][2];
            #pragma unroll
            for (int j = 0; j < 4; j++) {
                int n = wn * 32 + j * 8;
                bb[j][0] = Bs[(kk + t    ) * 136 + n + g];
                bb[j][1] = Bs[(kk + t + 4) * 136 + n + g];
            }
            #pragma unroll
            for (int ag = 0; ag < 4; ag++)
                #pragma unroll
                for (int j = 0; j < 4; j++)
                    mma_tf32(acc[ag][j], a[ag], bb[j][0], bb[j][1]);
        }
        __syncthreads();                 // done reading buf before next overwrite
    }

    // Epilogue: add bias, scale, round to tf32, store
    #pragma unroll
    for (int ag = 0; ag < 4; ag++) {
        int row = mt * 128 + wm * 64 + ag * 16 + g;
        #pragma unroll
        for (int j = 0; j < 4; j++) {
            int col = wn * 32 + j * 8 + 2 * t;           // 0..126 (even)
            int h   = h0 + (col >> 6);
            int ck  = col & 63;
            const float* bi = bias + (size_t)h * HD_;
            float b0 = bi[ck], b1 = bi[ck + 1];
            float* Ob = out + (size_t)(b * H_ + h) * S_ * HD_;
            uint2 v0 = make_uint2(f2tf((acc[ag][j][0] + b0) * sc),
                                  f2tf((acc[ag][j][1] + b1) * sc));
            uint2 v1 = make_uint2(f2tf((acc[ag][j][2] + b0) * sc),
                                  f2tf((acc[ag][j][3] + b1) * sc));
            *(uint2*)&Ob[(size_t)row * HD_ + ck]       = v0;
            *(uint2*)&Ob[(size_t)(row + 8) * HD_ + ck] = v1;
        }
    }
}

// ============================================================================
// Flash attention: one block = (b,h, 128-row Q tile). 128 threads (4 warps),
// warp owns 32 q-rows. K/V tiles (32 keys) double-buffered via cp.async
// (gmem already tf32 bits -> zero cvt in the loop). Q frags in registers.
// Dynamic smem 54272 B.
// ============================================================================
#define KS_TILE 2176            // 32*68 words
#define VS_TILE 2304            // 32*72 words
#define KS_OFF  0
#define VS_OFF  (2 * KS_TILE)                   // 4352
#define PS_OFF  (VS_OFF + 2 * VS_TILE)          // 8960
#define ATTN_SMEM_WORDS (PS_OFF + 128 * 36)     // 13568
#define ATTN_SMEM_BYTES (ATTN_SMEM_WORDS * 4)   // 54272

__global__ __launch_bounds__(128) void attn_kernel()
{
    extern __shared__ uint32_t dyn[];

    const int qt = blockIdx.x;          // 0..15 (S/128)
    const int bh = blockIdx.y;          // 0..31
    const int b  = bh >> 4;
    const int h  = bh & 15;
    const int q0 = qt * 128;

    const float* Qg = g_q + (size_t)bh * S_ * HD_;
    const float* Kg = g_k + (size_t)bh * S_ * HD_;
    const float* Vg = g_v + (size_t)bh * S_ * HD_;
    const uint32_t* Qu = (const uint32_t*)Qg;

    uint32_t* Ps = dyn + PS_OFF;        // [128][36]

    const int tid  = threadIdx.x;
    const int warp = tid >> 5;          // 0..3
    const int lane = tid & 31;
    const int g    = lane >> 2;
    const int t    = lane & 3;
    const int wrow = warp * 32;

    const uint32_t sbase = (uint32_t)__cvta_generic_to_shared(dyn);
    const int ldr  = tid >> 4;          // 0..7
    const int ldc4 = (tid & 15) * 4;    // 0..60

    // Q fragments (already tf32 + pre-scaled in gmem)
    uint32_t q[2][8][4];
    #pragma unroll
    for (int grp = 0; grp < 2; grp++) {
        int r0 = q0 + wrow + grp * 16 + g;
        #pragma unroll
        for (int kb = 0; kb < 8; kb++) {
            int c = kb * 8 + t;
            q[grp][kb][0] = Qu[(size_t)r0 * HD_ + c];
            q[grp][kb][1] = Qu[(size_t)(r0 + 8) * HD_ + c];
            q[grp][kb][2] = Qu[(size_t)r0 * HD_ + c + 4];
            q[grp][kb][3] = Qu[(size_t)(r0 + 8) * HD_ + c + 4];
        }
    }

    float o[2][8][4];
    #pragma unroll
    for (int grp = 0; grp < 2; grp++)
        #pragma unroll
        for (int j = 0; j < 8; j++)
            #pragma unroll
            for (int r = 0; r < 4; r++) o[grp][j][r] = 0.0f;
    float m[4] = {-INFINITY, -INFINITY, -INFINITY, -INFINITY};
    float l[4] = {0.0f, 0.0f, 0.0f, 0.0f};

    // Prologue: prefetch tile 0 into buffer 0
    {
        #pragma unroll
        for (int i = 0; i < 4; i++) {
            int rr = ldr + i * 8;
            CP_ASYNC16(sbase + (KS_OFF + rr * 68 + ldc4) * 4, Kg + (size_t)rr * HD_ + ldc4);
            CP_ASYNC16(sbase + (VS_OFF + rr * 72 + ldc4) * 4, Vg + (size_t)rr * HD_ + ldc4);
        }
        CP_COMMIT();
    }

    const int NT = S_ / 32;
    for (int kt = 0; kt < NT; kt++) {
        const int buf = kt & 1;
        CP_WAIT0();
        __syncthreads();                // all warps done with buf^1 from kt-1

        if (kt + 1 < NT) {              // prefetch next tile into buf^1
            const int nb = buf ^ 1;
            #pragma unroll
            for (int i = 0; i < 4; i++) {
                int rr = ldr + i * 8;
                size_t go = (size_t)((kt + 1) * 32 + rr) * HD_ + ldc4;
                CP_ASYNC16(sbase + (KS_OFF + nb * KS_TILE + rr * 68 + ldc4) * 4, Kg + go);
                CP_ASYNC16(sbase + (VS_OFF + nb * VS_TILE + rr * 72 + ldc4) * 4, Vg + go);
            }
        }
        CP_COMMIT();

        const uint32_t* KsB = dyn + KS_OFF + buf * KS_TILE;   // [32][68]
        const uint32_t* VsB = dyn + VS_OFF + buf * VS_TILE;   // [32][72]

        // S = Q K^T : 32 q-rows x 32 keys per warp
        float s[2][4][4];
        #pragma unroll
        for (int grp = 0; grp < 2; grp++)
            #pragma unroll
            for (int j = 0; j < 4; j++)
                #pragma unroll
                for (int r = 0; r < 4; r++) s[grp][j][r] = 0.0f;

        #pragma unroll
        for (int kb = 0; kb < 8; kb++) {
            const int kk = kb * 8;
            uint32_t bk_[4][2];
            #pragma unroll
            for (int j = 0; j < 4; j++) {
                bk_[j][0] = KsB[(j * 8 + g) * 68 + kk + t    ];
                bk_[j][1] = KsB[(j * 8 + g) * 68 + kk + t + 4];
            }
            #pragma unroll
            for (int grp = 0; grp < 2; grp++)
                #pragma unroll
                for (int j = 0; j < 4; j++)
                    mma_tf32(s[grp][j], q[grp][kb], bk_[j][0], bk_[j][1]);
        }

        // Online softmax per 16-row group
        #pragma unroll
        for (int grp = 0; grp < 2; grp++) {
            const int i0 = grp * 2, i1 = grp * 2 + 1;
            float mx0 = -INFINITY, mx1 = -INFINITY;
            #pragma unroll
            for (int j = 0; j < 4; j++) {
                mx0 = fmaxf(mx0, fmaxf(s[grp][j][0], s[grp][j][1]));
                mx1 = fmaxf(mx1, fmaxf(s[grp][j][2], s[grp][j][3]));
            }
            mx0 = fmaxf(mx0, __shfl_xor_sync(0xffffffff, mx0, 1));
            mx0 = fmaxf(mx0, __shfl_xor_sync(0xffffffff, mx0, 2));
            mx1 = fmaxf(mx1, __shfl_xor_sync(0xffffffff, mx1, 1));
            mx1 = fmaxf(mx1, __shfl_xor_sync(0xffffffff, mx1, 2));

            float mn0 = fmaxf(m[i0], mx0), mn1 = fmaxf(m[i1], mx1);
            float al0 = __expf(m[i0] - mn0), al1 = __expf(m[i1] - mn1);
            m[i0] = mn0; m[i1] = mn1;

            float sum0 = 0.0f, sum1 = 0.0f;
            int rp = wrow + grp * 16 + g;
            #pragma unroll
            for (int j = 0; j < 4; j++) {
                float p00 = __expf(s[grp][j][0] - mn0);
                float p01 = __expf(s[grp][j][1] - mn0);
                float p10 = __expf(s[grp][j][2] - mn1);
                float p11 = __expf(s[grp][j][3] - mn1);
                sum0 += p00 + p01;
                sum1 += p10 + p11;
                *(uint2*)&Ps[rp * 36 + j * 8 + 2 * t]       = make_uint2(f2tf(p00), f2tf(p01));
                *(uint2*)&Ps[(rp + 8) * 36 + j * 8 + 2 * t] = make_uint2(f2tf(p10), f2tf(p11));
            }
            sum0 += __shfl_xor_sync(0xffffffff, sum0, 1);
            sum0 += __shfl_xor_sync(0xffffffff, sum0, 2);
            sum1 += __shfl_xor_sync(0xffffffff, sum1, 1);
            sum1 += __shfl_xor_sync(0xffffffff, sum1, 2);
            l[i0] = l[i0] * al0 + sum0;
            l[i1] = l[i1] * al1 + sum1;

            #pragma unroll
            for (int j = 0; j < 8; j++) {
                o[grp][j][0] *= al0; o[grp][j][1] *= al0;
                o[grp][j][2] *= al1; o[grp][j][3] *= al1;
            }
        }
        __syncwarp();   // Ps rows are warp-private; order writes before reads

        // O += P V
        #pragma unroll
        for (int kb = 0; kb < 4; kb++) {
            const int kk = kb * 8;
            uint32_t a0[4], a1[4];
            {
                int rp = wrow + g;
                a0[0] = Ps[rp * 36 + kk + t    ];
                a0[1] = Ps[(rp + 8) * 36 + kk + t    ];
                a0[2] = Ps[rp * 36 + kk + t + 4];
                a0[3] = Ps[(rp + 8) * 36 + kk + t + 4];
                rp = wrow + 16 + g;
                a1[0] = Ps[rp * 36 + kk + t    ];
                a1[1] = Ps[(rp + 8) * 36 + kk + t    ];
                a1[2] = Ps[rp * 36 + kk + t + 4];
                a1[3] = Ps[(rp + 8) * 36 + kk + t + 4];
            }
            #pragma unroll
            for (int j = 0; j < 8; j++) {
                uint32_t b0 = VsB[(kk + t) * 72 + j * 8 + g];
                uint32_t b1 = VsB[(kk + t + 4) * 72 + j * 8 + g];
                mma_tf32(o[0][j], a0, b0, b1);
                mma_tf32(o[1][j], a1, b0, b1);
            }
        }
    }

    // Epilogue: normalize, scatter into [B,S,D] (concat heads)
    float inv[4] = {1.0f / l[0], 1.0f / l[1], 1.0f / l[2], 1.0f / l[3]};
    #pragma unroll
    for (int grp = 0; grp < 2; grp++) {
        #pragma unroll
        for (int j = 0; j < 8; j++) {
            int srow = q0 + wrow + grp * 16 + g;
            int col  = h * HD_ + j * 8 + 2 * t;
            *(float2*)&g_att[((size_t)b * S_ + srow) * D_ + col] =
                make_float2(o[grp][j][0] * inv[grp * 2], o[grp][j][1] * inv[grp * 2]);
            *(float2*)&g_att[((size_t)b * S_ + srow + 8) * D_ + col] =
                make_float2(o[grp][j][2] * inv[grp * 2 + 1], o[grp][j][3] * inv[grp * 2 + 1]);
        }
    }
}

// ============================================================================
// LayerNorm over last dim (1024). One block (256 thr) per row; float4 I/O.
// ============================================================================
__global__ __launch_bounds__(256) void ln_kernel(const float* __restrict__ gamma,
                                                 const float* __restrict__ beta,
                                                 float* __restrict__ out)
{
    const int row = blockIdx.x;
    const float* x = g_att + (size_t)row * D_;
    float*       y = out   + (size_t)row * D_;

    const int tid = threadIdx.x;
    float4 v = *(const float4*)&x[tid * 4];
    float sum = v.x + v.y + v.z + v.w;
    float sq  = v.x * v.x + v.y * v.y + v.z * v.z + v.w * v.w;

    #pragma unroll
    for (int off = 16; off > 0; off >>= 1) {
        sum += __shfl_down_sync(0xffffffff, sum, off);
        sq  += __shfl_down_sync(0xffffffff, sq,  off);
    }
    __shared__ float rs[8], rq[8], stats[2];
    int warp = tid >> 5, lane = tid & 31;
    if (lane == 0) { rs[warp] = sum; rq[warp] = sq; }
    __syncthreads();
    if (tid == 0) {
        float ts = 0.0f, tq = 0.0f;
        #pragma unroll
        for (int i = 0; i < 8; i++) { ts += rs[i]; tq += rq[i]; }
        float mean = ts * (1.0f / D_);
        float var  = tq * (1.0f / D_) - mean * mean;
        stats[0] = mean;
        stats[1] = rsqrtf(var + 1e-5f);
    }
    __syncthreads();
    float mean = stats[0], rstd = stats[1];

    float4 gm = *(const float4*)&gamma[tid * 4];
    float4 bt = *(const float4*)&beta[tid * 4];
    float4 r;
    r.x = (v.x - mean) * rstd * gm.x + bt.x;
    r.y = (v.y - mean) * rstd * gm.y + bt.y;
    r.z = (v.z - mean) * rstd * gm.z + bt.z;
    r.w = (v.w - mean) * rstd * gm.w + bt.w;
    *(float4*)&y[tid * 4] = r;
}

extern "C" void kernel_launch(void* const* d_in, const int* in_sizes, int n_in,
                              void* d_out, int out_size)
{
    (void)in_sizes; (void)n_in; (void)out_size;
    const float* queries = (const float*)d_in[0];
    const float* keys    = (const float*)d_in[1];
    const float* values  = (const float*)d_in[2];
    const float* Wq      = (const float*)d_in[3];
    const float* bq      = (const float*)d_in[4];
    const float* Wk      = (const float*)d_in[5];
    const float* bk      = (const float*)d_in[6];
    const float* Wv      = (const float*)d_in[7];
    const float* bv      = (const float*)d_in[8];
    const float* gamma   = (const float*)d_in[9];
    const float* beta    = (const float*)d_in[10];
    float* out = (float*)d_out;

    // Host-side module attributes (idempotent; set on the uncaptured
    // correctness call and persist).
    (void)cudaFuncSetAttribute(proj_kernel,
                               cudaFuncAttributeMaxDynamicSharedMemorySize,
                               PROJ_SMEM_BYTES);
    (void)cudaFuncSetAttribute(attn_kernel,
                               cudaFuncAttributeMaxDynamicSharedMemorySize,
                               ATTN_SMEM_BYTES);

    dim3 gp(S_ / 128, B_ * H_ / 2, 3);
    proj_kernel<<<gp, 256, PROJ_SMEM_BYTES>>>(queries, keys, values, Wq, Wk, Wv, bq, bk, bv);

    dim3 ga(S_ / 128, B_ * H_);
    attn_kernel<<<ga, 128, ATTN_SMEM_BYTES>>>();

    ln_kernel<<<B_ * S_, 256>>>(gamma, beta, out);
}